// round 1
// baseline (speedup 1.0000x reference)
#include <cuda_runtime.h>
#include <cuda_bf16.h>
#include <cstdint>

// LuGreCell: B=4096 batches, T=2048 steps, S=1, H=64.
// Kernel 1 (memory-bound): precompute per (b,t): v, k=g*sign(v),
//   c2 = dt*ln2*|v|/g, Fs; transpose to time-major [T][B] float4.
// Kernel 2 (MUFU-bound): sequential scan. 1024 warps, 4 batches/warp,
//   8 lanes/batch, 8 hidden/lane. tanh.approx on MUFU; softplus+exp fused
//   as exp2/log2 + Taylor.

#define BB 4096
#define TT 2048
#define HH 64

__device__ float4 g_pre[(size_t)BB * TT];  // 134 MB scratch (static, allowed)

__device__ __forceinline__ float ex2f_(float x){ float y; asm("ex2.approx.f32 %0, %1;":"=f"(y):"f"(x)); return y; }
__device__ __forceinline__ float lg2f_(float x){ float y; asm("lg2.approx.f32 %0, %1;":"=f"(y):"f"(x)); return y; }
__device__ __forceinline__ float tanhf_(float x){ float y; asm("tanh.approx.f32 %0, %1;":"=f"(y):"f"(x)); return y; }

#define LOG2E 1.4426950408889634f
#define C2COEF 6.931471805599453e-4f        /* dt*ln2 */
#define INVC   1442.6950408889634f          /* 1/(dt*ln2) */

// ---------------- Kernel 1: precompute + transpose ----------------
__global__ void __launch_bounds__(256) lugre_pre(
    const float* __restrict__ x,        // [B, T, 3]: v, F_c, F_s
    const float* __restrict__ alpha,    // [1]
    const float* __restrict__ vs)       // [1]
{
    __shared__ float4 tile[32][33];
    const int t0 = blockIdx.x * 32;
    const int b0 = blockIdx.y * 32;
    const float a0  = alpha[0];
    const float lvs = lg2f_(fabsf(vs[0]));
    const int tx = threadIdx.x, ty = threadIdx.y;

    #pragma unroll
    for (int i = 0; i < 4; i++) {
        int bl = ty + 8 * i;
        size_t base = ((size_t)(b0 + bl) * TT + (t0 + tx)) * 3;
        float v  = x[base];
        float Fc = x[base + 1];
        float Fs = x[base + 2];
        float av = fabsf(v);
        // p = |v/vs|^alpha ; w = exp(-p) ; g = Fc + (Fs-Fc)*w
        float p  = ex2f_(a0 * (lg2f_(av) - lvs));
        float w  = ex2f_(-LOG2E * p);
        float g  = fmaf(Fs - Fc, w, Fc);
        float sg = (v > 0.f) ? 1.f : ((v < 0.f) ? -1.f : 0.f);
        float k  = g * sg;
        float c2 = __fdividef(av, g) * C2COEF;  // dt*ln2*|v|/g
        tile[bl][tx] = make_float4(v, k, c2, Fs);
    }
    __syncthreads();
    #pragma unroll
    for (int i = 0; i < 4; i++) {
        int tl = ty + 8 * i;
        g_pre[(size_t)(t0 + tl) * BB + (b0 + tx)] = tile[tx][tl];
    }
}

// ---------------- Kernel 2: sequential scan ----------------
__device__ __forceinline__ float lugre_step(
    float4 pk, float& sz,
    const float* w0, const float* w1r, const float* bbv, const float* w2s,
    float b2s8, float s1, float s2)
{
    float v = pk.x, k = pk.y, c2 = pk.z, Fs = pk.w;
    float invg = c2 * INVC;          // |v|/g
    float d = sz - k;                // off critical path start
    float h[8];
    #pragma unroll
    for (int q = 0; q < 8; q++) {
        float z = fmaf(sz, w1r[q], fmaf(v, w0[q], bbv[q]));
        h[q] = tanhf_(z);
    }
    float a0 = fmaf(h[0], w2s[0], b2s8);
    float a1 = h[1] * w2s[1];
    a0 = fmaf(h[2], w2s[2], a0);
    a1 = fmaf(h[3], w2s[3], a1);
    a0 = fmaf(h[4], w2s[4], a0);
    a1 = fmaf(h[5], w2s[5], a1);
    a0 = fmaf(h[6], w2s[6], a0);
    a1 = fmaf(h[7], w2s[7], a1);
    float part = a0 + a1;
    part += __shfl_xor_sync(0xffffffffu, part, 1);
    part += __shfl_xor_sync(0xffffffffu, part, 2);
    part += __shfl_xor_sync(0xffffffffu, part, 4);   // y' = (h.W2 + b2)*log2e
    // decay = exp(-c*softplus) = exp2(-c2/ln2 * ln2*log2(1+2^y')) -> Taylor in u
    float e  = ex2f_(part);
    float Lg = lg2f_(1.0f + e);
    float u  = c2 * Lg;                       // u = dt*sigma0*|v|/g  (small)
    float rr = fmaf(u, 0.16666667f, -0.5f);
    float qq = fmaf(u, rr, 1.0f);
    float m  = u * qq;                        // m = 1 - exp(-u) (3-term)
    float szn = fmaf(-d, m, sz);              // pre-clip sz
    float zd  = fmaf(-szn, invg, v);          // zdot uses pre-clip sz
    float szc = fminf(fmaxf(szn, -Fs), Fs);
    float F   = fmaf(s1, zd, fmaf(s2, v, szc));
    sz = szc;
    return F;
}

__global__ void __launch_bounds__(256) lugre_scan(
    const float* __restrict__ W1, const float* __restrict__ b1,
    const float* __restrict__ W2, const float* __restrict__ b2,
    const float* __restrict__ sg1, const float* __restrict__ sg2,
    float* __restrict__ out)
{
    const int lane = threadIdx.x & 31;
    const int warp = (blockIdx.x * blockDim.x + threadIdx.x) >> 5;  // 0..1023
    const int slot = lane >> 3;     // 0..3 : batch slot in warp
    const int r    = lane & 7;      // 0..7 : lane within batch group
    const int b    = warp * 4 + slot;

    float w0[8], w1r[8], bbv[8], w2s[8];
    #pragma unroll
    for (int q = 0; q < 8; q++) {
        int j = r * 8 + q;
        w0[q]  = W1[j];             // W1[0][j]
        w1r[q] = W1[HH + j];        // W1[1][j]
        bbv[q] = b1[j];
        w2s[q] = W2[j] * LOG2E;     // fold log2e into W2
    }
    const float b2s8 = b2[0] * LOG2E * 0.125f;  // b2 split over 8 lanes
    const float s1 = fabsf(sg1[0]);
    const float s2 = fabsf(sg2[0]);

    const float4* p = g_pre + b;
    float* outp = out + (size_t)b * TT;

    float4 c0 = p[0], c1 = p[BB], c2v = p[2 * BB], c3 = p[3 * BB];
    float4 n0 = c0, n1 = c1, n2 = c2v, n3 = c3;
    float sz = 0.0f;

    for (int tb = 0; tb < TT; tb += 4) {
        if (tb + 4 < TT) {
            const float4* pn = p + (size_t)(tb + 4) * BB;
            n0 = pn[0]; n1 = pn[BB]; n2 = pn[2 * BB]; n3 = pn[3 * BB];
        }
        float f0 = lugre_step(c0,  sz, w0, w1r, bbv, w2s, b2s8, s1, s2);
        float f1 = lugre_step(c1,  sz, w0, w1r, bbv, w2s, b2s8, s1, s2);
        float f2 = lugre_step(c2v, sz, w0, w1r, bbv, w2s, b2s8, s1, s2);
        float f3 = lugre_step(c3,  sz, w0, w1r, bbv, w2s, b2s8, s1, s2);
        if (r == 0) {
            *reinterpret_cast<float4*>(outp + tb) = make_float4(f0, f1, f2, f3);
        }
        c0 = n0; c1 = n1; c2v = n2; c3 = n3;
    }
}

// ---------------- launch ----------------
extern "C" void kernel_launch(void* const* d_in, const int* in_sizes, int n_in,
                              void* d_out, int out_size) {
    const float* x     = (const float*)d_in[0];
    const float* sig1  = (const float*)d_in[1];
    const float* sig2  = (const float*)d_in[2];
    const float* alpha = (const float*)d_in[3];
    const float* vs    = (const float*)d_in[4];
    const float* W1    = (const float*)d_in[5];
    const float* b1    = (const float*)d_in[6];
    const float* W2    = (const float*)d_in[7];
    const float* b2    = (const float*)d_in[8];
    float* out = (float*)d_out;

    dim3 blk(32, 8);
    dim3 grd(TT / 32, BB / 32);
    lugre_pre<<<grd, blk>>>(x, alpha, vs);

    lugre_scan<<<128, 256>>>(W1, b1, W2, b2, sig1, sig2, out);
}